// round 15
// baseline (speedup 1.0000x reference)
#include <cuda_runtime.h>
#include <cstdint>

// Problem constants
#define B_  8
#define S_  4096
#define D_  1024
#define KK  32      // E*P = 8*4

// Output layout: flat concat of (expert_weights, expert_indices, phi_weights,
// soft_slots, expert_inputs), all as float32.
#define OFF0 0              // expert_weights [B,S,E]      262144
#define OFF1 262144         // expert_indices [B,S,E]      262144
#define OFF2 524288         // phi_weights    [B,S,E,P]    1048576
#define OFF3 1572864        // soft_slots     [B,E,P,D]    262144
#define OFF4 1835008        // expert_inputs  [B,E,P*D]    262144

#define NSPLIT 16           // S-splits in phaseC
#define NHALF  4            // D-splits in phaseA

// Scratch (device globals: no allocation allowed)
__device__ float  g_Lh[NHALF][B_ * KK * S_];     // logit partials (16 MB); [0] holds sum
__device__ float  g_part[B_ * NSPLIT * KK * D_]; // split-K partials (16 MB)
__device__ float2 g_ms[B_ * KK];                 // per-(b,k) {max, inv_sum}

__device__ __forceinline__ unsigned long long fma2(unsigned long long a,
                                                   unsigned long long b,
                                                   unsigned long long c) {
    unsigned long long d;
    asm("fma.rn.f32x2 %0, %1, %2, %3;" : "=l"(d) : "l"(a), "l"(b), "l"(c));
    return d;
}
__device__ __forceinline__ unsigned long long dup2(float p) {
    unsigned long long d;
    asm("mov.b64 %0, {%1, %1};" : "=l"(d) : "f"(p));
    return d;
}
__device__ __forceinline__ float2 unpack2(unsigned long long v) {
    float2 r;
    asm("mov.b64 {%0, %1}, %2;" : "=f"(r.x), "=f"(r.y) : "l"(v));
    return r;
}
__device__ __forceinline__ void cpa16(uint32_t dst, const void* src) {
    asm volatile("cp.async.cg.shared.global [%0], [%1], 16;" :: "r"(dst), "l"(src));
}
__device__ __forceinline__ void cpa_commit() {
    asm volatile("cp.async.commit_group;");
}
__device__ __forceinline__ uint32_t smem_u32(const void* p) {
    uint32_t a;
    asm("{ .reg .u64 t; cvta.to.shared.u64 t, %1; cvt.u32.u64 %0, t; }" : "=r"(a) : "l"(p));
    return a;
}

// ---------------------------------------------------------------------------
// Phase A: partial logits over a quarter of D, cp.async double-buffered,
// 32-d subtiles. Grid 1024: bid = tile*4 + half.
// Phi pairs loaded as 2x LDS.128 (8 contiguous words) instead of 4x LDS.64.
// ---------------------------------------------------------------------------
__global__ void __launch_bounds__(128) phaseA(const float* __restrict__ x,
                                              const float* __restrict__ phiK,
                                              const float* __restrict__ bias) {
    __shared__ __align__(16) float xs[2][128][36]; // [buf][tok][d] (+pad)
    __shared__ __align__(16) float ps[2][32][32];  // [buf][d][k]

    const int tid  = threadIdx.x;
    const int bid  = blockIdx.x;
    const int half = bid & 3;
    const int tile = bid >> 2;
    const int tok0 = tile * 128;                // never crosses a batch
    const int b    = tok0 / S_;
    const int s0   = tok0 - b * S_;
    const int kt   = tid & 3;                   // k-group: 8 k = 4 pairs
    const int tokt = tid >> 2;                  // token lane: 4 tokens stride 32

    unsigned long long acc[4][4];               // [token i][k-pair j]
    #pragma unroll
    for (int i = 0; i < 4; i++)
        #pragma unroll
        for (int j = 0; j < 4; j++) acc[i][j] = 0ull;

    const float* xbase = x + (size_t)tok0 * D_ + half * 256;

    auto load_tile = [&](int tb, int dt) {
        const int dbase = dt * 32;
        #pragma unroll
        for (int j = 0; j < 8; j++) {           // x: 128 tok x 32 d = 1024 chunks
            int chunk = tid + j * 128;
            int row = chunk >> 3;
            int c   = chunk & 7;
            cpa16(smem_u32(&xs[tb][row][c * 4]),
                  xbase + (size_t)row * D_ + dbase + c * 4);
        }
        #pragma unroll
        for (int j = 0; j < 2; j++) {           // phi: 32 d x 32 k = 256 chunks
            int chunk = tid + j * 128;
            int d = chunk >> 3;
            int c = chunk & 7;
            cpa16(smem_u32(&ps[tb][d][c * 4]),
                  phiK + (size_t)(half * 256 + dbase + d) * KK + c * 4);
        }
        cpa_commit();
    };

    load_tile(0, 0);

    #pragma unroll
    for (int t = 0; t < 8; t++) {
        if (t < 7) load_tile((t + 1) & 1, t + 1);
        if (t < 7) asm volatile("cp.async.wait_group 1;" ::: "memory");
        else       asm volatile("cp.async.wait_group 0;" ::: "memory");
        __syncthreads();

        const int tb = t & 1;
        #pragma unroll 8
        for (int d = 0; d < 32; d++) {
            ulonglong2 pA = *(const ulonglong2*)&ps[tb][d][kt * 8 + 0];
            ulonglong2 pB = *(const ulonglong2*)&ps[tb][d][kt * 8 + 4];
            #pragma unroll
            for (int i = 0; i < 4; i++) {
                unsigned long long xv = dup2(xs[tb][tokt + 32 * i][d]);
                acc[i][0] = fma2(xv, pA.x, acc[i][0]);
                acc[i][1] = fma2(xv, pA.y, acc[i][1]);
                acc[i][2] = fma2(xv, pB.x, acc[i][2]);
                acc[i][3] = fma2(xv, pB.y, acc[i][3]);
            }
        }
        __syncthreads();
    }

    float bv[8];
    #pragma unroll
    for (int j = 0; j < 8; j++)
        bv[j] = (half == 0) ? bias[kt * 8 + j] : 0.f;

    float* Ldst = g_Lh[half] + (size_t)b * KK * S_ + s0;
    #pragma unroll
    for (int i = 0; i < 4; i++) {
        int tok = tokt + 32 * i;
        #pragma unroll
        for (int j = 0; j < 4; j++) {
            float2 v = unpack2(acc[i][j]);
            int k0 = kt * 8 + 2 * j;
            Ldst[(size_t)k0 * S_ + tok]       = v.x + bv[2 * j];
            Ldst[(size_t)(k0 + 1) * S_ + tok] = v.y + bv[2 * j + 1];
        }
    }
}

// ---------------------------------------------------------------------------
// Phase B1: sum the 4 logit partials (write back to g_Lh[0]) and compute
// per-(b,k) softmax stats {max, 1/sum(exp)}. float4 loads.
// ---------------------------------------------------------------------------
__global__ void __launch_bounds__(256) phaseB1() {
    const int bk  = blockIdx.x;       // b*32 + k
    const int tid = threadIdx.x;
    const size_t base4 = (size_t)bk * (S_ / 4);
    float4* L0       = (float4*)g_Lh[0] + base4;
    const float4* L1 = (const float4*)g_Lh[1] + base4;
    const float4* L2 = (const float4*)g_Lh[2] + base4;
    const float4* L3 = (const float4*)g_Lh[3] + base4;

    __shared__ float red[8];

    float4 v[4];
    float m = -1e30f;
    #pragma unroll
    for (int i = 0; i < 4; i++) {
        int idx = tid + i * 256;
        float4 a = L0[idx], b4 = L1[idx], c = L2[idx], d = L3[idx];
        a.x += b4.x + c.x + d.x;
        a.y += b4.y + c.y + d.y;
        a.z += b4.z + c.z + d.z;
        a.w += b4.w + c.w + d.w;
        v[i] = a;
        L0[idx] = a;
        m = fmaxf(m, fmaxf(fmaxf(a.x, a.y), fmaxf(a.z, a.w)));
    }
    #pragma unroll
    for (int o = 16; o > 0; o >>= 1) m = fmaxf(m, __shfl_xor_sync(0xffffffffu, m, o));
    if ((tid & 31) == 0) red[tid >> 5] = m;
    __syncthreads();
    if (tid < 32) {
        float t = (tid < 8) ? red[tid] : -1e30f;
        #pragma unroll
        for (int o = 4; o > 0; o >>= 1) t = fmaxf(t, __shfl_xor_sync(0xffffffffu, t, o));
        if (tid == 0) red[0] = t;
    }
    __syncthreads();
    m = red[0];
    __syncthreads();

    float s = 0.f;
    #pragma unroll
    for (int i = 0; i < 4; i++) {
        s += __expf(v[i].x - m) + __expf(v[i].y - m)
           + __expf(v[i].z - m) + __expf(v[i].w - m);
    }
    #pragma unroll
    for (int o = 16; o > 0; o >>= 1) s += __shfl_xor_sync(0xffffffffu, s, o);
    if ((tid & 31) == 0) red[tid >> 5] = s;
    __syncthreads();
    if (tid < 32) {
        float t = (tid < 8) ? red[tid] : 0.f;
        #pragma unroll
        for (int o = 4; o > 0; o >>= 1) t += __shfl_xor_sync(0xffffffffu, t, o);
        if (tid == 0) red[0] = t;
    }
    __syncthreads();
    if (tid == 0) {
        float2 r; r.x = m; r.y = 1.0f / red[0];
        g_ms[bk] = r;
    }
}

// ---------------------------------------------------------------------------
// Phase B2: normalize + transpose; also fills expert_weights (1/E) and
// expert_indices (constant pattern) using idle bandwidth here.
// ---------------------------------------------------------------------------
__global__ void __launch_bounds__(128) phaseB2(float* __restrict__ out) {
    const int bid = blockIdx.x;           // b*32 + stile
    const int b   = bid >> 5;
    const int s0  = (bid & 31) * 128;
    const int tid = threadIdx.x;

    __shared__ float  sm[32][129];
    __shared__ float2 ms[32];

    if (tid < 32) ms[tid] = g_ms[b * KK + tid];
    __syncthreads();

    #pragma unroll
    for (int k = 0; k < 32; k++) {
        float v = g_Lh[0][((size_t)b * KK + k) * S_ + s0 + tid];
        sm[k][tid] = __expf(v - ms[k].x) * ms[k].y;
    }
    __syncthreads();

    float* dst = out + OFF2 + ((size_t)b * S_ + s0 + tid) * KK;
    #pragma unroll
    for (int k4 = 0; k4 < 8; k4++) {
        float4 v;
        v.x = sm[k4 * 4 + 0][tid];
        v.y = sm[k4 * 4 + 1][tid];
        v.z = sm[k4 * 4 + 2][tid];
        v.w = sm[k4 * 4 + 3][tid];
        *(float4*)&dst[k4 * 4] = v;
    }

    // constant outputs: 32768 threads x 2 float4 per region
    float4* out4 = (float4*)out;
    const int gt = bid * 128 + tid;
    #pragma unroll
    for (int j = 0; j < 2; j++) {
        int idx = gt + j * 32768;       // 0..65535
        out4[OFF0 / 4 + idx] = make_float4(0.125f, 0.125f, 0.125f, 0.125f);
        float e0 = (float)((4 * idx) & 7);
        out4[OFF1 / 4 + idx] = make_float4(e0, e0 + 1.f, e0 + 2.f, e0 + 3.f);
    }
}

// ---------------------------------------------------------------------------
// Phase C: 16-row subtiles, 3-stage ring, 7 CTAs/SM. Thread's d-pairs are
// ADJACENT: {2td, 2td+1, 2td+32, 2td+33} -> x loads are 2x LDS.128
// (contiguous 256 B per 16 lanes, conflict-free) and stores are STG.128.
// Per-r shared loads: 3 (was 5) -> lifts the L1/LSU bound.
// ---------------------------------------------------------------------------
__global__ void __launch_bounds__(128, 7) phaseC(const float* __restrict__ x,
                                                 const float* __restrict__ out) {
    const int bid = blockIdx.x;
    const int b   = bid >> 7;
    const int dt  = (bid >> 4) & 7;
    const int sp  = bid & 15;
    const int dbase = dt * 128;
    const int tid = threadIdx.x;
    const int td  = tid & 15;   // d-group lane (4 floats at 4*td, 4 more at 64+4*td)
    const int tk  = tid >> 4;   // k group: 4 contiguous k

    __shared__ __align__(16) float xt[3][16][132]; // [buf][s][d]
    __shared__ __align__(16) float ws[3][16][36];  // [buf][s][k]

    unsigned long long acc[4][4]; // [kk][pair j]: j=0,1 -> floats 4td..4td+3; j=2,3 -> 64+4td..
    #pragma unroll
    for (int i = 0; i < 4; i++)
        #pragma unroll
        for (int j = 0; j < 4; j++) acc[i][j] = 0ull;

    const float* w    = out + OFF2 + (size_t)b * S_ * KK;
    const float* xrow = x + (size_t)b * S_ * D_ + dbase;

    auto load_tile = [&](int tb, int t) {
        const int sb = sp * 256 + t * 16;
        #pragma unroll
        for (int j = 0; j < 4; j++) {          // x: 16 rows x 128 f = 512 chunks
            int chunk = tid + j * 128;
            int row = chunk >> 5;
            int c   = chunk & 31;
            cpa16(smem_u32(&xt[tb][row][c * 4]),
                  xrow + (size_t)(sb + row) * D_ + c * 4);
        }
        {                                      // w: 16 rows x 32 f = 128 chunks
            int row = tid >> 3;
            int c   = tid & 7;
            cpa16(smem_u32(&ws[tb][row][c * 4]),
                  w + (size_t)(sb + row) * KK + c * 4);
        }
        cpa_commit();
    };

    load_tile(0, 0);
    load_tile(1, 1);

    for (int t = 0; t < 16; t++) {
        if (t < 14) {
            load_tile((t + 2) % 3, t + 2);
            asm volatile("cp.async.wait_group 2;" ::: "memory");
        } else if (t == 14) {
            asm volatile("cp.async.wait_group 1;" ::: "memory");
        } else {
            asm volatile("cp.async.wait_group 0;" ::: "memory");
        }
        __syncthreads();

        const int tb = t % 3;
        #pragma unroll 8
        for (int r = 0; r < 16; r++) {
            float4 wv = *(const float4*)&ws[tb][r][tk * 4];
            unsigned long long w0 = dup2(wv.x), w1 = dup2(wv.y),
                               w2 = dup2(wv.z), w3 = dup2(wv.w);
            ulonglong2 xa = *(const ulonglong2*)&xt[tb][r][td * 4];      // pairs 2td,2td+1
            ulonglong2 xb = *(const ulonglong2*)&xt[tb][r][td * 4 + 64]; // pairs 2td+32,2td+33
            acc[0][0] = fma2(xa.x, w0, acc[0][0]);
            acc[0][1] = fma2(xa.y, w0, acc[0][1]);
            acc[0][2] = fma2(xb.x, w0, acc[0][2]);
            acc[0][3] = fma2(xb.y, w0, acc[0][3]);
            acc[1][0] = fma2(xa.x, w1, acc[1][0]);
            acc[1][1] = fma2(xa.y, w1, acc[1][1]);
            acc[1][2] = fma2(xb.x, w1, acc[1][2]);
            acc[1][3] = fma2(xb.y, w1, acc[1][3]);
            acc[2][0] = fma2(xa.x, w2, acc[2][0]);
            acc[2][1] = fma2(xa.y, w2, acc[2][1]);
            acc[2][2] = fma2(xb.x, w2, acc[2][2]);
            acc[2][3] = fma2(xb.y, w2, acc[2][3]);
            acc[3][0] = fma2(xa.x, w3, acc[3][0]);
            acc[3][1] = fma2(xa.y, w3, acc[3][1]);
            acc[3][2] = fma2(xb.x, w3, acc[3][2]);
            acc[3][3] = fma2(xb.y, w3, acc[3][3]);
        }
        __syncthreads();
    }

    #pragma unroll
    for (int kk = 0; kk < 4; kk++) {
        int k = tk * 4 + kk;
        float* dst = &g_part[(((size_t)b * NSPLIT + sp) * KK + k) * D_ + dbase];
        ulonglong2 vA; vA.x = acc[kk][0]; vA.y = acc[kk][1];
        ulonglong2 vB; vB.x = acc[kk][2]; vB.y = acc[kk][3];
        *(ulonglong2*)&dst[td * 4]      = vA;   // floats 4td..4td+3
        *(ulonglong2*)&dst[td * 4 + 64] = vB;   // floats 64+4td..
    }
}

// ---------------------------------------------------------------------------
// Phase D: reduce split-K partials into soft_slots + expert_inputs.
// ---------------------------------------------------------------------------
__global__ void __launch_bounds__(256) phaseD(float* __restrict__ out) {
    const int i4 = blockIdx.x * 256 + threadIdx.x; // 65536 float4 threads
    const int b  = i4 >> 13;                       // / (KK*D/4)
    const int rem4 = i4 & 8191;

    const float4* part4 = (const float4*)g_part;
    float4 a = make_float4(0.f, 0.f, 0.f, 0.f);
    #pragma unroll
    for (int sp = 0; sp < NSPLIT; sp++) {
        float4 p = part4[((size_t)b * NSPLIT + sp) * (KK * D_ / 4) + rem4];
        a.x += p.x; a.y += p.y; a.z += p.z; a.w += p.w;
    }
    float4* out4 = (float4*)out;
    out4[OFF3 / 4 + i4] = a;        // soft_slots [B,E,P,D]
    out4[OFF4 / 4 + i4] = a;        // expert_inputs [B,E,P*D] (same layout)
}

extern "C" void kernel_launch(void* const* d_in, const int* in_sizes, int n_in,
                              void* d_out, int out_size) {
    const float* x    = (const float*)d_in[0];
    const float* phiK = (const float*)d_in[1];
    const float* bias = (const float*)d_in[2];
    float* out = (float*)d_out;

    phaseA<<<1024, 128>>>(x, phiK, bias);
    phaseB1<<<256, 256>>>();
    phaseB2<<<256, 128>>>(out);
    phaseC<<<1024, 128>>>(x, out);
    phaseD<<<256, 256>>>(out);
}

// round 16
// speedup vs baseline: 1.0273x; 1.0273x over previous
#include <cuda_runtime.h>
#include <cstdint>

// Problem constants
#define B_  8
#define S_  4096
#define D_  1024
#define KK  32      // E*P = 8*4

// Output layout: flat concat of (expert_weights, expert_indices, phi_weights,
// soft_slots, expert_inputs), all as float32.
#define OFF0 0              // expert_weights [B,S,E]      262144
#define OFF1 262144         // expert_indices [B,S,E]      262144
#define OFF2 524288         // phi_weights    [B,S,E,P]    1048576
#define OFF3 1572864        // soft_slots     [B,E,P,D]    262144
#define OFF4 1835008        // expert_inputs  [B,E,P*D]    262144

#define NSPLIT 16           // S-splits in phaseC
#define NHALF  4            // D-splits in phaseA

// Scratch (device globals: no allocation allowed)
__device__ float  g_Lh[NHALF][B_ * KK * S_];     // logit partials (16 MB); [0] holds sum
__device__ float  g_part[B_ * NSPLIT * KK * D_]; // split-K partials (16 MB)
__device__ float2 g_ms[B_ * KK];                 // per-(b,k) {max, inv_sum}

__device__ __forceinline__ unsigned long long fma2(unsigned long long a,
                                                   unsigned long long b,
                                                   unsigned long long c) {
    unsigned long long d;
    asm("fma.rn.f32x2 %0, %1, %2, %3;" : "=l"(d) : "l"(a), "l"(b), "l"(c));
    return d;
}
__device__ __forceinline__ unsigned long long dup2(float p) {
    unsigned long long d;
    asm("mov.b64 %0, {%1, %1};" : "=l"(d) : "f"(p));
    return d;
}
__device__ __forceinline__ float2 unpack2(unsigned long long v) {
    float2 r;
    asm("mov.b64 {%0, %1}, %2;" : "=f"(r.x), "=f"(r.y) : "l"(v));
    return r;
}
__device__ __forceinline__ void cpa16(uint32_t dst, const void* src) {
    asm volatile("cp.async.cg.shared.global [%0], [%1], 16;" :: "r"(dst), "l"(src));
}
__device__ __forceinline__ void cpa_commit() {
    asm volatile("cp.async.commit_group;");
}
__device__ __forceinline__ uint32_t smem_u32(const void* p) {
    uint32_t a;
    asm("{ .reg .u64 t; cvta.to.shared.u64 t, %1; cvt.u32.u64 %0, t; }" : "=r"(a) : "l"(p));
    return a;
}

// ---------------------------------------------------------------------------
// Phase A: partial logits over a quarter of D, cp.async double-buffered,
// 32-d subtiles. Grid 1024: bid = tile*4 + half.
// Phi pairs loaded as 2x LDS.128 (8 contiguous words).
// ---------------------------------------------------------------------------
__global__ void __launch_bounds__(128) phaseA(const float* __restrict__ x,
                                              const float* __restrict__ phiK,
                                              const float* __restrict__ bias) {
    __shared__ __align__(16) float xs[2][128][36]; // [buf][tok][d] (+pad)
    __shared__ __align__(16) float ps[2][32][32];  // [buf][d][k]

    const int tid  = threadIdx.x;
    const int bid  = blockIdx.x;
    const int half = bid & 3;
    const int tile = bid >> 2;
    const int tok0 = tile * 128;                // never crosses a batch
    const int b    = tok0 / S_;
    const int s0   = tok0 - b * S_;
    const int kt   = tid & 3;                   // k-group: 8 k = 4 pairs
    const int tokt = tid >> 2;                  // token lane: 4 tokens stride 32

    unsigned long long acc[4][4];               // [token i][k-pair j]
    #pragma unroll
    for (int i = 0; i < 4; i++)
        #pragma unroll
        for (int j = 0; j < 4; j++) acc[i][j] = 0ull;

    const float* xbase = x + (size_t)tok0 * D_ + half * 256;

    auto load_tile = [&](int tb, int dt) {
        const int dbase = dt * 32;
        #pragma unroll
        for (int j = 0; j < 8; j++) {           // x: 128 tok x 32 d = 1024 chunks
            int chunk = tid + j * 128;
            int row = chunk >> 3;
            int c   = chunk & 7;
            cpa16(smem_u32(&xs[tb][row][c * 4]),
                  xbase + (size_t)row * D_ + dbase + c * 4);
        }
        #pragma unroll
        for (int j = 0; j < 2; j++) {           // phi: 32 d x 32 k = 256 chunks
            int chunk = tid + j * 128;
            int d = chunk >> 3;
            int c = chunk & 7;
            cpa16(smem_u32(&ps[tb][d][c * 4]),
                  phiK + (size_t)(half * 256 + dbase + d) * KK + c * 4);
        }
        cpa_commit();
    };

    load_tile(0, 0);

    #pragma unroll
    for (int t = 0; t < 8; t++) {
        if (t < 7) load_tile((t + 1) & 1, t + 1);
        if (t < 7) asm volatile("cp.async.wait_group 1;" ::: "memory");
        else       asm volatile("cp.async.wait_group 0;" ::: "memory");
        __syncthreads();

        const int tb = t & 1;
        #pragma unroll 8
        for (int d = 0; d < 32; d++) {
            ulonglong2 pA = *(const ulonglong2*)&ps[tb][d][kt * 8 + 0];
            ulonglong2 pB = *(const ulonglong2*)&ps[tb][d][kt * 8 + 4];
            #pragma unroll
            for (int i = 0; i < 4; i++) {
                unsigned long long xv = dup2(xs[tb][tokt + 32 * i][d]);
                acc[i][0] = fma2(xv, pA.x, acc[i][0]);
                acc[i][1] = fma2(xv, pA.y, acc[i][1]);
                acc[i][2] = fma2(xv, pB.x, acc[i][2]);
                acc[i][3] = fma2(xv, pB.y, acc[i][3]);
            }
        }
        __syncthreads();
    }

    float bv[8];
    #pragma unroll
    for (int j = 0; j < 8; j++)
        bv[j] = (half == 0) ? bias[kt * 8 + j] : 0.f;

    float* Ldst = g_Lh[half] + (size_t)b * KK * S_ + s0;
    #pragma unroll
    for (int i = 0; i < 4; i++) {
        int tok = tokt + 32 * i;
        #pragma unroll
        for (int j = 0; j < 4; j++) {
            float2 v = unpack2(acc[i][j]);
            int k0 = kt * 8 + 2 * j;
            Ldst[(size_t)k0 * S_ + tok]       = v.x + bv[2 * j];
            Ldst[(size_t)(k0 + 1) * S_ + tok] = v.y + bv[2 * j + 1];
        }
    }
}

// ---------------------------------------------------------------------------
// Phase B1: sum the 4 logit partials (write back to g_Lh[0]) and compute
// per-(b,k) softmax stats {max, 1/sum(exp)}. 1024 threads/block (4x the
// residency of the old 256-thr version), 1 float4 per thread.
// ---------------------------------------------------------------------------
__global__ void __launch_bounds__(1024) phaseB1() {
    const int bk  = blockIdx.x;       // b*32 + k
    const int tid = threadIdx.x;      // 0..1023 (= S/4 float4 slots)
    const size_t base4 = (size_t)bk * (S_ / 4);
    float4* L0       = (float4*)g_Lh[0] + base4;
    const float4* L1 = (const float4*)g_Lh[1] + base4;
    const float4* L2 = (const float4*)g_Lh[2] + base4;
    const float4* L3 = (const float4*)g_Lh[3] + base4;

    __shared__ float red[32];
    const int wid = tid >> 5;
    const int ln  = tid & 31;

    float4 a = L0[tid];
    {
        float4 b4 = L1[tid], c = L2[tid], d = L3[tid];
        a.x += b4.x + c.x + d.x;
        a.y += b4.y + c.y + d.y;
        a.z += b4.z + c.z + d.z;
        a.w += b4.w + c.w + d.w;
    }
    L0[tid] = a;

    float m = fmaxf(fmaxf(a.x, a.y), fmaxf(a.z, a.w));
    #pragma unroll
    for (int o = 16; o > 0; o >>= 1) m = fmaxf(m, __shfl_xor_sync(0xffffffffu, m, o));
    if (ln == 0) red[wid] = m;
    __syncthreads();
    if (tid < 32) {
        float t = red[tid];
        #pragma unroll
        for (int o = 16; o > 0; o >>= 1) t = fmaxf(t, __shfl_xor_sync(0xffffffffu, t, o));
        if (tid == 0) red[0] = t;
    }
    __syncthreads();
    m = red[0];
    __syncthreads();

    float s = __expf(a.x - m) + __expf(a.y - m) + __expf(a.z - m) + __expf(a.w - m);
    #pragma unroll
    for (int o = 16; o > 0; o >>= 1) s += __shfl_xor_sync(0xffffffffu, s, o);
    if (ln == 0) red[wid] = s;
    __syncthreads();
    if (tid < 32) {
        float t = red[tid];
        #pragma unroll
        for (int o = 16; o > 0; o >>= 1) t += __shfl_xor_sync(0xffffffffu, t, o);
        if (tid == 0) red[0] = t;
    }
    __syncthreads();
    if (tid == 0) {
        float2 r; r.x = m; r.y = 1.0f / red[0];
        g_ms[bk] = r;
    }
}

// ---------------------------------------------------------------------------
// Phase B2: normalize + transpose; also fills expert_weights (1/E) and
// expert_indices (constant pattern) using idle bandwidth here.
// ---------------------------------------------------------------------------
__global__ void __launch_bounds__(128) phaseB2(float* __restrict__ out) {
    const int bid = blockIdx.x;           // b*32 + stile
    const int b   = bid >> 5;
    const int s0  = (bid & 31) * 128;
    const int tid = threadIdx.x;

    __shared__ float  sm[32][129];
    __shared__ float2 ms[32];

    if (tid < 32) ms[tid] = g_ms[b * KK + tid];
    __syncthreads();

    #pragma unroll
    for (int k = 0; k < 32; k++) {
        float v = g_Lh[0][((size_t)b * KK + k) * S_ + s0 + tid];
        sm[k][tid] = __expf(v - ms[k].x) * ms[k].y;
    }
    __syncthreads();

    float* dst = out + OFF2 + ((size_t)b * S_ + s0 + tid) * KK;
    #pragma unroll
    for (int k4 = 0; k4 < 8; k4++) {
        float4 v;
        v.x = sm[k4 * 4 + 0][tid];
        v.y = sm[k4 * 4 + 1][tid];
        v.z = sm[k4 * 4 + 2][tid];
        v.w = sm[k4 * 4 + 3][tid];
        *(float4*)&dst[k4 * 4] = v;
    }

    // constant outputs: 32768 threads x 2 float4 per region
    float4* out4 = (float4*)out;
    const int gt = bid * 128 + tid;
    #pragma unroll
    for (int j = 0; j < 2; j++) {
        int idx = gt + j * 32768;       // 0..65535
        out4[OFF0 / 4 + idx] = make_float4(0.125f, 0.125f, 0.125f, 0.125f);
        float e0 = (float)((4 * idx) & 7);
        out4[OFF1 / 4 + idx] = make_float4(e0, e0 + 1.f, e0 + 2.f, e0 + 3.f);
    }
}

// ---------------------------------------------------------------------------
// Phase C (R13 measured-good form): 16-row subtiles, 3-stage ring, 7 CTAs/SM,
// strided LDS.64 d-pairs + LDS.128 w + dup2.
// ---------------------------------------------------------------------------
__global__ void __launch_bounds__(128, 7) phaseC(const float* __restrict__ x,
                                                 const float* __restrict__ out) {
    const int bid = blockIdx.x;
    const int b   = bid >> 7;
    const int dt  = (bid >> 4) & 7;
    const int sp  = bid & 15;
    const int dbase = dt * 128;
    const int tid = threadIdx.x;
    const int td  = tid & 15;   // d-pair lane
    const int tk  = tid >> 4;   // k group: 4 contiguous k

    __shared__ __align__(16) float xt[3][16][132]; // [buf][s][d]
    __shared__ __align__(16) float ws[3][16][36];  // [buf][s][k]

    unsigned long long acc[4][4]; // [kk][d-pair i]
    #pragma unroll
    for (int i = 0; i < 4; i++)
        #pragma unroll
        for (int j = 0; j < 4; j++) acc[i][j] = 0ull;

    const float* w    = out + OFF2 + (size_t)b * S_ * KK;
    const float* xrow = x + (size_t)b * S_ * D_ + dbase;

    auto load_tile = [&](int tb, int t) {
        const int sb = sp * 256 + t * 16;
        #pragma unroll
        for (int j = 0; j < 4; j++) {          // x: 16 rows x 128 f = 512 chunks
            int chunk = tid + j * 128;
            int row = chunk >> 5;
            int c   = chunk & 31;
            cpa16(smem_u32(&xt[tb][row][c * 4]),
                  xrow + (size_t)(sb + row) * D_ + c * 4);
        }
        {                                      // w: 16 rows x 32 f = 128 chunks
            int row = tid >> 3;
            int c   = tid & 7;
            cpa16(smem_u32(&ws[tb][row][c * 4]),
                  w + (size_t)(sb + row) * KK + c * 4);
        }
        cpa_commit();
    };

    load_tile(0, 0);
    load_tile(1, 1);

    for (int t = 0; t < 16; t++) {
        if (t < 14) {
            load_tile((t + 2) % 3, t + 2);
            asm volatile("cp.async.wait_group 2;" ::: "memory");
        } else if (t == 14) {
            asm volatile("cp.async.wait_group 1;" ::: "memory");
        } else {
            asm volatile("cp.async.wait_group 0;" ::: "memory");
        }
        __syncthreads();

        const int tb = t % 3;
        #pragma unroll 8
        for (int r = 0; r < 16; r++) {
            float4 wv = *(const float4*)&ws[tb][r][tk * 4];
            unsigned long long w0 = dup2(wv.x), w1 = dup2(wv.y),
                               w2 = dup2(wv.z), w3 = dup2(wv.w);
            #pragma unroll
            for (int i = 0; i < 4; i++) {
                unsigned long long xv =
                    *(const unsigned long long*)&xt[tb][r][(td + 16 * i) * 2];
                acc[0][i] = fma2(xv, w0, acc[0][i]);
                acc[1][i] = fma2(xv, w1, acc[1][i]);
                acc[2][i] = fma2(xv, w2, acc[2][i]);
                acc[3][i] = fma2(xv, w3, acc[3][i]);
            }
        }
        __syncthreads();
    }

    #pragma unroll
    for (int kk = 0; kk < 4; kk++) {
        int k = tk * 4 + kk;
        float* dst = &g_part[(((size_t)b * NSPLIT + sp) * KK + k) * D_ + dbase];
        #pragma unroll
        for (int i = 0; i < 4; i++) {
            float2 v = unpack2(acc[kk][i]);
            *(float2*)&dst[(td + 16 * i) * 2] = v;
        }
    }
}

// ---------------------------------------------------------------------------
// Phase D: reduce split-K partials into soft_slots + expert_inputs.
// 2 threads per output (8 splits each), shfl_xor combine. Grid 512x256.
// ---------------------------------------------------------------------------
__global__ void __launch_bounds__(256) phaseD(float* __restrict__ out) {
    const int gid = blockIdx.x * 256 + threadIdx.x; // 131072 threads
    const int i4   = gid >> 1;                      // output float4 index
    const int half = gid & 1;
    const int b    = i4 >> 13;                      // / (KK*D/4)
    const int rem4 = i4 & 8191;

    const float4* part4 = (const float4*)g_part;
    float4 a = make_float4(0.f, 0.f, 0.f, 0.f);
    #pragma unroll
    for (int j = 0; j < 8; j++) {
        int sp = half * 8 + j;
        float4 p = part4[((size_t)b * NSPLIT + sp) * (KK * D_ / 4) + rem4];
        a.x += p.x; a.y += p.y; a.z += p.z; a.w += p.w;
    }
    a.x += __shfl_xor_sync(0xffffffffu, a.x, 1);
    a.y += __shfl_xor_sync(0xffffffffu, a.y, 1);
    a.z += __shfl_xor_sync(0xffffffffu, a.z, 1);
    a.w += __shfl_xor_sync(0xffffffffu, a.w, 1);

    if (half == 0) {
        float4* out4 = (float4*)out;
        out4[OFF3 / 4 + i4] = a;    // soft_slots [B,E,P,D]
        out4[OFF4 / 4 + i4] = a;    // expert_inputs [B,E,P*D] (same layout)
    }
}

extern "C" void kernel_launch(void* const* d_in, const int* in_sizes, int n_in,
                              void* d_out, int out_size) {
    const float* x    = (const float*)d_in[0];
    const float* phiK = (const float*)d_in[1];
    const float* bias = (const float*)d_in[2];
    float* out = (float*)d_out;

    phaseA<<<1024, 128>>>(x, phiK, bias);
    phaseB1<<<256, 1024>>>();
    phaseB2<<<256, 128>>>(out);
    phaseC<<<1024, 128>>>(x, out);
    phaseD<<<512, 256>>>(out);
}

// round 17
// speedup vs baseline: 1.0320x; 1.0045x over previous
#include <cuda_runtime.h>
#include <cstdint>

// Problem constants
#define B_  8
#define S_  4096
#define D_  1024
#define KK  32      // E*P = 8*4

// Output layout: flat concat of (expert_weights, expert_indices, phi_weights,
// soft_slots, expert_inputs), all as float32.
#define OFF0 0              // expert_weights [B,S,E]      262144
#define OFF1 262144         // expert_indices [B,S,E]      262144
#define OFF2 524288         // phi_weights    [B,S,E,P]    1048576
#define OFF3 1572864        // soft_slots     [B,E,P,D]    262144
#define OFF4 1835008        // expert_inputs  [B,E,P*D]    262144

#define NSPLIT 16           // S-splits in phaseC
#define NHALF  4            // D-splits in phaseA

// Scratch (device globals: no allocation allowed)
__device__ float  g_Lh[NHALF][B_ * KK * S_];     // logit partials (16 MB); [0] holds sum
__device__ float  g_part[B_ * NSPLIT * KK * D_]; // split-K partials (16 MB)
__device__ float2 g_ms[B_ * KK];                 // per-(b,k) {max, inv_sum}

__device__ __forceinline__ unsigned long long fma2(unsigned long long a,
                                                   unsigned long long b,
                                                   unsigned long long c) {
    unsigned long long d;
    asm("fma.rn.f32x2 %0, %1, %2, %3;" : "=l"(d) : "l"(a), "l"(b), "l"(c));
    return d;
}
__device__ __forceinline__ unsigned long long dup2(float p) {
    unsigned long long d;
    asm("mov.b64 %0, {%1, %1};" : "=l"(d) : "f"(p));
    return d;
}
__device__ __forceinline__ float2 unpack2(unsigned long long v) {
    float2 r;
    asm("mov.b64 {%0, %1}, %2;" : "=f"(r.x), "=f"(r.y) : "l"(v));
    return r;
}
__device__ __forceinline__ void cpa16(uint32_t dst, const void* src) {
    asm volatile("cp.async.cg.shared.global [%0], [%1], 16;" :: "r"(dst), "l"(src));
}
__device__ __forceinline__ void cpa_commit() {
    asm volatile("cp.async.commit_group;");
}
__device__ __forceinline__ uint32_t smem_u32(const void* p) {
    uint32_t a;
    asm("{ .reg .u64 t; cvta.to.shared.u64 t, %1; cvt.u32.u64 %0, t; }" : "=r"(a) : "l"(p));
    return a;
}

// ---------------------------------------------------------------------------
// Phase A: partial logits over a quarter of D, cp.async double-buffered,
// 32-d subtiles. Grid 1024: bid = tile*4 + half.
// Phi pairs loaded as 2x LDS.128 (8 contiguous words).
// ---------------------------------------------------------------------------
__global__ void __launch_bounds__(128) phaseA(const float* __restrict__ x,
                                              const float* __restrict__ phiK,
                                              const float* __restrict__ bias) {
    __shared__ __align__(16) float xs[2][128][36]; // [buf][tok][d] (+pad)
    __shared__ __align__(16) float ps[2][32][32];  // [buf][d][k]

    const int tid  = threadIdx.x;
    const int bid  = blockIdx.x;
    const int half = bid & 3;
    const int tile = bid >> 2;
    const int tok0 = tile * 128;                // never crosses a batch
    const int b    = tok0 / S_;
    const int s0   = tok0 - b * S_;
    const int kt   = tid & 3;                   // k-group: 8 k = 4 pairs
    const int tokt = tid >> 2;                  // token lane: 4 tokens stride 32

    unsigned long long acc[4][4];               // [token i][k-pair j]
    #pragma unroll
    for (int i = 0; i < 4; i++)
        #pragma unroll
        for (int j = 0; j < 4; j++) acc[i][j] = 0ull;

    const float* xbase = x + (size_t)tok0 * D_ + half * 256;

    auto load_tile = [&](int tb, int dt) {
        const int dbase = dt * 32;
        #pragma unroll
        for (int j = 0; j < 8; j++) {           // x: 128 tok x 32 d = 1024 chunks
            int chunk = tid + j * 128;
            int row = chunk >> 3;
            int c   = chunk & 7;
            cpa16(smem_u32(&xs[tb][row][c * 4]),
                  xbase + (size_t)row * D_ + dbase + c * 4);
        }
        #pragma unroll
        for (int j = 0; j < 2; j++) {           // phi: 32 d x 32 k = 256 chunks
            int chunk = tid + j * 128;
            int d = chunk >> 3;
            int c = chunk & 7;
            cpa16(smem_u32(&ps[tb][d][c * 4]),
                  phiK + (size_t)(half * 256 + dbase + d) * KK + c * 4);
        }
        cpa_commit();
    };

    load_tile(0, 0);

    #pragma unroll
    for (int t = 0; t < 8; t++) {
        if (t < 7) load_tile((t + 1) & 1, t + 1);
        if (t < 7) asm volatile("cp.async.wait_group 1;" ::: "memory");
        else       asm volatile("cp.async.wait_group 0;" ::: "memory");
        __syncthreads();

        const int tb = t & 1;
        #pragma unroll 8
        for (int d = 0; d < 32; d++) {
            ulonglong2 pA = *(const ulonglong2*)&ps[tb][d][kt * 8 + 0];
            ulonglong2 pB = *(const ulonglong2*)&ps[tb][d][kt * 8 + 4];
            #pragma unroll
            for (int i = 0; i < 4; i++) {
                unsigned long long xv = dup2(xs[tb][tokt + 32 * i][d]);
                acc[i][0] = fma2(xv, pA.x, acc[i][0]);
                acc[i][1] = fma2(xv, pA.y, acc[i][1]);
                acc[i][2] = fma2(xv, pB.x, acc[i][2]);
                acc[i][3] = fma2(xv, pB.y, acc[i][3]);
            }
        }
        __syncthreads();
    }

    float bv[8];
    #pragma unroll
    for (int j = 0; j < 8; j++)
        bv[j] = (half == 0) ? bias[kt * 8 + j] : 0.f;

    float* Ldst = g_Lh[half] + (size_t)b * KK * S_ + s0;
    #pragma unroll
    for (int i = 0; i < 4; i++) {
        int tok = tokt + 32 * i;
        #pragma unroll
        for (int j = 0; j < 4; j++) {
            float2 v = unpack2(acc[i][j]);
            int k0 = kt * 8 + 2 * j;
            Ldst[(size_t)k0 * S_ + tok]       = v.x + bv[2 * j];
            Ldst[(size_t)(k0 + 1) * S_ + tok] = v.y + bv[2 * j + 1];
        }
    }
}

// ---------------------------------------------------------------------------
// Phase B1: sum the 4 logit partials (write back to g_Lh[0]) and compute
// per-(b,k) softmax stats {max, 1/sum(exp)}. 1024 threads/block.
// ---------------------------------------------------------------------------
__global__ void __launch_bounds__(1024) phaseB1() {
    const int bk  = blockIdx.x;       // b*32 + k
    const int tid = threadIdx.x;      // 0..1023 (= S/4 float4 slots)
    const size_t base4 = (size_t)bk * (S_ / 4);
    float4* L0       = (float4*)g_Lh[0] + base4;
    const float4* L1 = (const float4*)g_Lh[1] + base4;
    const float4* L2 = (const float4*)g_Lh[2] + base4;
    const float4* L3 = (const float4*)g_Lh[3] + base4;

    __shared__ float red[32];
    const int wid = tid >> 5;
    const int ln  = tid & 31;

    float4 a = L0[tid];
    {
        float4 b4 = L1[tid], c = L2[tid], d = L3[tid];
        a.x += b4.x + c.x + d.x;
        a.y += b4.y + c.y + d.y;
        a.z += b4.z + c.z + d.z;
        a.w += b4.w + c.w + d.w;
    }
    L0[tid] = a;

    float m = fmaxf(fmaxf(a.x, a.y), fmaxf(a.z, a.w));
    #pragma unroll
    for (int o = 16; o > 0; o >>= 1) m = fmaxf(m, __shfl_xor_sync(0xffffffffu, m, o));
    if (ln == 0) red[wid] = m;
    __syncthreads();
    if (tid < 32) {
        float t = red[tid];
        #pragma unroll
        for (int o = 16; o > 0; o >>= 1) t = fmaxf(t, __shfl_xor_sync(0xffffffffu, t, o));
        if (tid == 0) red[0] = t;
    }
    __syncthreads();
    m = red[0];
    __syncthreads();

    float s = __expf(a.x - m) + __expf(a.y - m) + __expf(a.z - m) + __expf(a.w - m);
    #pragma unroll
    for (int o = 16; o > 0; o >>= 1) s += __shfl_xor_sync(0xffffffffu, s, o);
    if (ln == 0) red[wid] = s;
    __syncthreads();
    if (tid < 32) {
        float t = red[tid];
        #pragma unroll
        for (int o = 16; o > 0; o >>= 1) t += __shfl_xor_sync(0xffffffffu, t, o);
        if (tid == 0) red[0] = t;
    }
    __syncthreads();
    if (tid == 0) {
        float2 r; r.x = m; r.y = 1.0f / red[0];
        g_ms[bk] = r;
    }
}

// ---------------------------------------------------------------------------
// Phase B2: normalize + transpose; also fills expert_weights (1/E) and
// expert_indices (constant pattern) using idle bandwidth here.
// ---------------------------------------------------------------------------
__global__ void __launch_bounds__(128) phaseB2(float* __restrict__ out) {
    const int bid = blockIdx.x;           // b*32 + stile
    const int b   = bid >> 5;
    const int s0  = (bid & 31) * 128;
    const int tid = threadIdx.x;

    __shared__ float  sm[32][129];
    __shared__ float2 ms[32];

    if (tid < 32) ms[tid] = g_ms[b * KK + tid];
    __syncthreads();

    #pragma unroll
    for (int k = 0; k < 32; k++) {
        float v = g_Lh[0][((size_t)b * KK + k) * S_ + s0 + tid];
        sm[k][tid] = __expf(v - ms[k].x) * ms[k].y;
    }
    __syncthreads();

    float* dst = out + OFF2 + ((size_t)b * S_ + s0 + tid) * KK;
    #pragma unroll
    for (int k4 = 0; k4 < 8; k4++) {
        float4 v;
        v.x = sm[k4 * 4 + 0][tid];
        v.y = sm[k4 * 4 + 1][tid];
        v.z = sm[k4 * 4 + 2][tid];
        v.w = sm[k4 * 4 + 3][tid];
        *(float4*)&dst[k4 * 4] = v;
    }

    // constant outputs: 32768 threads x 2 float4 per region
    float4* out4 = (float4*)out;
    const int gt = bid * 128 + tid;
    #pragma unroll
    for (int j = 0; j < 2; j++) {
        int idx = gt + j * 32768;       // 0..65535
        out4[OFF0 / 4 + idx] = make_float4(0.125f, 0.125f, 0.125f, 0.125f);
        float e0 = (float)((4 * idx) & 7);
        out4[OFF1 / 4 + idx] = make_float4(e0, e0 + 1.f, e0 + 2.f, e0 + 3.f);
    }
}

// ---------------------------------------------------------------------------
// Phase C: 16-row subtiles, 3-stage ring, 7 CTAs/SM. SINGLE barrier per
// subtile: prefetch for t+2 issued at the BOTTOM of iteration t (its target
// buffer's last reader was iteration t-1, fenced by the top barrier of t).
// Group accounting: 2 init commits + 1 commit/iter => wait_group 1 at top
// guarantees tile t has landed.
// ---------------------------------------------------------------------------
__global__ void __launch_bounds__(128, 7) phaseC(const float* __restrict__ x,
                                                 const float* __restrict__ out) {
    const int bid = blockIdx.x;
    const int b   = bid >> 7;
    const int dt  = (bid >> 4) & 7;
    const int sp  = bid & 15;
    const int dbase = dt * 128;
    const int tid = threadIdx.x;
    const int td  = tid & 15;   // d-pair lane
    const int tk  = tid >> 4;   // k group: 4 contiguous k

    __shared__ __align__(16) float xt[3][16][132]; // [buf][s][d]
    __shared__ __align__(16) float ws[3][16][36];  // [buf][s][k]

    unsigned long long acc[4][4]; // [kk][d-pair i]
    #pragma unroll
    for (int i = 0; i < 4; i++)
        #pragma unroll
        for (int j = 0; j < 4; j++) acc[i][j] = 0ull;

    const float* w    = out + OFF2 + (size_t)b * S_ * KK;
    const float* xrow = x + (size_t)b * S_ * D_ + dbase;

    auto load_tile = [&](int tb, int t) {
        const int sb = sp * 256 + t * 16;
        #pragma unroll
        for (int j = 0; j < 4; j++) {          // x: 16 rows x 128 f = 512 chunks
            int chunk = tid + j * 128;
            int row = chunk >> 5;
            int c   = chunk & 31;
            cpa16(smem_u32(&xt[tb][row][c * 4]),
                  xrow + (size_t)(sb + row) * D_ + c * 4);
        }
        {                                      // w: 16 rows x 32 f = 128 chunks
            int row = tid >> 3;
            int c   = tid & 7;
            cpa16(smem_u32(&ws[tb][row][c * 4]),
                  w + (size_t)(sb + row) * KK + c * 4);
        }
        cpa_commit();
    };

    load_tile(0, 0);
    load_tile(1, 1);

    for (int t = 0; t < 16; t++) {
        if (t < 15) asm volatile("cp.async.wait_group 1;" ::: "memory");
        else        asm volatile("cp.async.wait_group 0;" ::: "memory");
        __syncthreads();           // tile t visible; prior readers of (t+2)%3 done

        const int tb = t % 3;
        #pragma unroll 8
        for (int r = 0; r < 16; r++) {
            float4 wv = *(const float4*)&ws[tb][r][tk * 4];
            unsigned long long w0 = dup2(wv.x), w1 = dup2(wv.y),
                               w2 = dup2(wv.z), w3 = dup2(wv.w);
            #pragma unroll
            for (int i = 0; i < 4; i++) {
                unsigned long long xv =
                    *(const unsigned long long*)&xt[tb][r][(td + 16 * i) * 2];
                acc[0][i] = fma2(xv, w0, acc[0][i]);
                acc[1][i] = fma2(xv, w1, acc[1][i]);
                acc[2][i] = fma2(xv, w2, acc[2][i]);
                acc[3][i] = fma2(xv, w3, acc[3][i]);
            }
        }

        if (t < 14) load_tile((t + 2) % 3, t + 2);  // bottom-issued prefetch
    }

    #pragma unroll
    for (int kk = 0; kk < 4; kk++) {
        int k = tk * 4 + kk;
        float* dst = &g_part[(((size_t)b * NSPLIT + sp) * KK + k) * D_ + dbase];
        #pragma unroll
        for (int i = 0; i < 4; i++) {
            float2 v = unpack2(acc[kk][i]);
            *(float2*)&dst[(td + 16 * i) * 2] = v;
        }
    }
}

// ---------------------------------------------------------------------------
// Phase D: reduce split-K partials into soft_slots + expert_inputs.
// 2 threads per output (8 splits each), shfl_xor combine. Grid 512x256.
// ---------------------------------------------------------------------------
__global__ void __launch_bounds__(256) phaseD(float* __restrict__ out) {
    const int gid = blockIdx.x * 256 + threadIdx.x; // 131072 threads
    const int i4   = gid >> 1;                      // output float4 index
    const int half = gid & 1;
    const int b    = i4 >> 13;                      // / (KK*D/4)
    const int rem4 = i4 & 8191;

    const float4* part4 = (const float4*)g_part;
    float4 a = make_float4(0.f, 0.f, 0.f, 0.f);
    #pragma unroll
    for (int j = 0; j < 8; j++) {
        int sp = half * 8 + j;
        float4 p = part4[((size_t)b * NSPLIT + sp) * (KK * D_ / 4) + rem4];
        a.x += p.x; a.y += p.y; a.z += p.z; a.w += p.w;
    }
    a.x += __shfl_xor_sync(0xffffffffu, a.x, 1);
    a.y += __shfl_xor_sync(0xffffffffu, a.y, 1);
    a.z += __shfl_xor_sync(0xffffffffu, a.z, 1);
    a.w += __shfl_xor_sync(0xffffffffu, a.w, 1);

    if (half == 0) {
        float4* out4 = (float4*)out;
        out4[OFF3 / 4 + i4] = a;    // soft_slots [B,E,P,D]
        out4[OFF4 / 4 + i4] = a;    // expert_inputs [B,E,P*D] (same layout)
    }
}

extern "C" void kernel_launch(void* const* d_in, const int* in_sizes, int n_in,
                              void* d_out, int out_size) {
    const float* x    = (const float*)d_in[0];
    const float* phiK = (const float*)d_in[1];
    const float* bias = (const float*)d_in[2];
    float* out = (float*)d_out;

    phaseA<<<1024, 128>>>(x, phiK, bias);
    phaseB1<<<256, 1024>>>();
    phaseB2<<<256, 128>>>(out);
    phaseC<<<1024, 128>>>(x, out);
    phaseD<<<512, 256>>>(out);
}